// round 5
// baseline (speedup 1.0000x reference)
#include <cuda_runtime.h>

#define NEG_SLOPE 0.2f
#define LN_EPS 1e-5f

static const int MAXN = 50000;
static const int MAXE = 800000;

// Scratch (allocation-free: __device__ globals; BSS zero-init at load)
__device__ float g_xl[MAXN * 64];
__device__ float g_xr[MAXN * 64];
__device__ int   g_deg[MAXN];      // invariant: zero at kernel_launch entry
__device__ int   g_scan[MAXN];
__device__ int   g_ptr[MAXN + 1];
__device__ int   g_fill[MAXN];
__device__ int   g_csrc[MAXE];
__device__ int   g_tilesum[128];
__device__ int   g_bar1, g_bar2;   // grid barrier state (self-resetting)

// ---------------------------------------------------------------------------
// K1: xl = x@Wl + bl, xr = x@Wr + br.  8 nodes per warp (weights amortized in
// registers, fma.rn.f32x2 packed), 64 nodes per 256-thread block.
// Tail: fused in-degree histogram (g_deg zero at entry; K3 restores).
// ---------------------------------------------------------------------------
__global__ void linear_hist_kernel(const float* __restrict__ x,
                                   const float* __restrict__ Wl, const float* __restrict__ bl,
                                   const float* __restrict__ Wr, const float* __restrict__ br,
                                   const int* __restrict__ dst,
                                   int n, int E) {
    __shared__ __align__(16) float sWl[64 * 64];
    __shared__ __align__(16) float sWr[64 * 64];
    __shared__ __align__(16) float sx[64 * 64];
    int tid = threadIdx.x;
    for (int i = tid; i < 4096; i += 256) { sWl[i] = Wl[i]; sWr[i] = Wr[i]; }

    int base = blockIdx.x * 64;
    for (int i = tid; i < 4096; i += 256) {
        int nn = base + (i >> 6);
        sx[i] = (nn < n) ? x[nn * 64 + (i & 63)] : 0.f;
    }
    __syncthreads();

    int w = tid >> 5;
    int j = tid & 31;
    {
        unsigned long long accl[8], accr[8];
#pragma unroll
        for (int k = 0; k < 8; k++) { accl[k] = 0ull; accr[k] = 0ull; }

        const unsigned long long* wl2 = reinterpret_cast<const unsigned long long*>(sWl + 2 * j);
        const unsigned long long* wr2 = reinterpret_cast<const unsigned long long*>(sWr + 2 * j);
        const float* xv = sx + (w * 8) * 64;

#pragma unroll 8
        for (int c = 0; c < 64; c++) {
            unsigned long long wl = wl2[c * 32];
            unsigned long long wr = wr2[c * 32];
#pragma unroll
            for (int k = 0; k < 8; k++) {
                float xc = xv[k * 64 + c];
                unsigned long long x2;
                asm("mov.b64 %0, {%1, %1};" : "=l"(x2) : "f"(xc));
                asm("fma.rn.f32x2 %0, %1, %2, %0;" : "+l"(accl[k]) : "l"(x2), "l"(wl));
                asm("fma.rn.f32x2 %0, %1, %2, %0;" : "+l"(accr[k]) : "l"(x2), "l"(wr));
            }
        }

        float2 bl2 = *reinterpret_cast<const float2*>(bl + 2 * j);
        float2 br2 = *reinterpret_cast<const float2*>(br + 2 * j);
#pragma unroll
        for (int k = 0; k < 8; k++) {
            int nn = base + w * 8 + k;
            if (nn < n) {
                float l0, l1, r0, r1;
                asm("mov.b64 {%0, %1}, %2;" : "=f"(l0), "=f"(l1) : "l"(accl[k]));
                asm("mov.b64 {%0, %1}, %2;" : "=f"(r0), "=f"(r1) : "l"(accr[k]));
                *reinterpret_cast<float2*>(g_xl + nn * 64 + 2 * j) =
                    make_float2(l0 + bl2.x, l1 + bl2.y);
                *reinterpret_cast<float2*>(g_xr + nn * 64 + 2 * j) =
                    make_float2(r0 + br2.x, r1 + br2.y);
            }
        }
    }

    // fused in-degree histogram (grid-stride over edges)
    int stride = gridDim.x * 256;
    for (int e = blockIdx.x * 256 + tid; e < E; e += stride)
        atomicAdd(&g_deg[dst[e]], 1);
}

// ---------------------------------------------------------------------------
// K2: per-tile (1024) inclusive scan of g_deg -> g_scan; tile totals.
// ---------------------------------------------------------------------------
__global__ void scan1_kernel(int n) {
    __shared__ int wsum[32];
    int gid = blockIdx.x * 1024 + threadIdx.x;
    int lane = threadIdx.x & 31, wid = threadIdx.x >> 5;
    int v = (gid < n) ? g_deg[gid] : 0;
    int s = v;
#pragma unroll
    for (int o = 1; o < 32; o <<= 1) {
        int t = __shfl_up_sync(0xFFFFFFFFu, s, o);
        if (lane >= o) s += t;
    }
    if (lane == 31) wsum[wid] = s;
    __syncthreads();
    if (wid == 0) {
        int wv = wsum[lane];
#pragma unroll
        for (int o = 1; o < 32; o <<= 1) {
            int t = __shfl_up_sync(0xFFFFFFFFu, wv, o);
            if (lane >= o) wv += t;
        }
        wsum[lane] = wv;
    }
    __syncthreads();
    int incl = s + (wid ? wsum[wid - 1] : 0);
    if (gid < n) g_scan[gid] = incl;
    if (threadIdx.x == 1023) g_tilesum[blockIdx.x] = incl;
}

// ---------------------------------------------------------------------------
// K3: apply tile offsets -> g_ptr/g_fill, re-zero g_deg; then a software grid
// barrier (all <=49 blocks co-resident); then the CSR scatter with 8 edges in
// flight per thread. Barrier self-resets before exit (graph-replay safe).
// ---------------------------------------------------------------------------
__global__ void scan3_scatter_kernel(const int* __restrict__ src, const int* __restrict__ dst,
                                     int n, int E) {
    __shared__ int s_off;
    int t = threadIdx.x;
    if (t < 32) {
        int acc = 0;
        for (int i = t; i < blockIdx.x; i += 32) acc += g_tilesum[i];
#pragma unroll
        for (int o = 16; o; o >>= 1) acc += __shfl_xor_sync(0xFFFFFFFFu, acc, o);
        if (t == 0) s_off = acc;
    }
    __syncthreads();
    int gid = blockIdx.x * 1024 + t;
    if (gid < n) {
        int incl = g_scan[gid] + s_off;
        int excl = incl - g_deg[gid];
        g_ptr[gid]  = excl;
        g_fill[gid] = excl;
        g_deg[gid]  = 0;
        if (gid == n - 1) g_ptr[n] = incl;
    }

    // ---- grid barrier (all blocks resident: gridDim.x <= 148) ----
    __syncthreads();
    if (t == 0) {
        __threadfence();
        atomicAdd(&g_bar1, 1);
        while (atomicAdd(&g_bar1, 0) < (int)gridDim.x) {}
        int r = atomicAdd(&g_bar2, 1);
        if (r == (int)gridDim.x - 1) { g_bar1 = 0; g_bar2 = 0; }
    }
    __syncthreads();

    // ---- scatter: 8 edges per thread per stride step ----
    int nthreads = gridDim.x * 1024;
    for (long long i = (long long)(blockIdx.x * 1024 + t) * 8; i < E; i += (long long)nthreads * 8) {
        if (i + 7 < E) {
            int4 d4a = *reinterpret_cast<const int4*>(dst + i);
            int4 d4b = *reinterpret_cast<const int4*>(dst + i + 4);
            int4 s4a = *reinterpret_cast<const int4*>(src + i);
            int4 s4b = *reinterpret_cast<const int4*>(src + i + 4);
            int p0 = atomicAdd(&g_fill[d4a.x], 1);
            int p1 = atomicAdd(&g_fill[d4a.y], 1);
            int p2 = atomicAdd(&g_fill[d4a.z], 1);
            int p3 = atomicAdd(&g_fill[d4a.w], 1);
            int p4 = atomicAdd(&g_fill[d4b.x], 1);
            int p5 = atomicAdd(&g_fill[d4b.y], 1);
            int p6 = atomicAdd(&g_fill[d4b.z], 1);
            int p7 = atomicAdd(&g_fill[d4b.w], 1);
            g_csrc[p0] = s4a.x;
            g_csrc[p1] = s4a.y;
            g_csrc[p2] = s4a.z;
            g_csrc[p3] = s4a.w;
            g_csrc[p4] = s4b.x;
            g_csrc[p5] = s4b.y;
            g_csrc[p6] = s4b.z;
            g_csrc[p7] = s4b.w;
        } else {
            for (long long e = i; e < E; e++) {
                int p = atomicAdd(&g_fill[dst[e]], 1);
                g_csrc[p] = src[e];
            }
        }
    }
}

// ---------------------------------------------------------------------------
// K4: fused per-node GAT aggregation + bias + residual + LayerNorm + ELU.
// One warp per destination node; 2 channels per lane; 8 edges in flight.
// ---------------------------------------------------------------------------
__global__ void gat_node_kernel(const float* __restrict__ x, const float* __restrict__ att,
                                const float* __restrict__ bias, const float* __restrict__ gamma,
                                const float* __restrict__ beta, float* __restrict__ out, int n) {
    int warp = (blockIdx.x * blockDim.x + threadIdx.x) >> 5;
    int lane = threadIdx.x & 31;
    if (warp >= n) return;
    int d = warp;
    int i0 = d * 64 + 2 * lane;

    float2 xr2  = __ldg(reinterpret_cast<const float2*>(g_xr + i0));
    float2 attv = *reinterpret_cast<const float2*>(att + 2 * lane);

    int start = __ldg(&g_ptr[d]), end = __ldg(&g_ptr[d + 1]);
    float accx = 0.f, accy = 0.f, denom = 0.f;

    for (int base = start; base < end; base += 32) {
        int cnt = min(32, end - base);
        int sv = (lane < cnt) ? __ldg(&g_csrc[base + lane]) : 0;

        for (int j = 0; j < cnt; j += 8) {
            float2 c[8];
            float  w[8];
#pragma unroll
            for (int k = 0; k < 8; k++) {
                int jj = j + k;
                int s = __shfl_sync(0xFFFFFFFFu, sv, jj);
                c[k] = __ldg(reinterpret_cast<const float2*>(g_xl + s * 64 + 2 * lane));
                w[k] = (jj < cnt) ? 1.f : 0.f;
            }
            float p[8];
#pragma unroll
            for (int k = 0; k < 8; k++) {
                float vx = c[k].x + xr2.x, vy = c[k].y + xr2.y;
                vx = vx > 0.f ? vx : NEG_SLOPE * vx;
                vy = vy > 0.f ? vy : NEG_SLOPE * vy;
                p[k] = fmaf(vx, attv.x, vy * attv.y);
            }
#pragma unroll
            for (int k = 0; k < 8; k++) p[k] += __shfl_xor_sync(0xFFFFFFFFu, p[k], 1);
#pragma unroll
            for (int k = 0; k < 8; k++) p[k] += __shfl_xor_sync(0xFFFFFFFFu, p[k], 2);
#pragma unroll
            for (int k = 0; k < 8; k++) p[k] += __shfl_xor_sync(0xFFFFFFFFu, p[k], 4);
#pragma unroll
            for (int k = 0; k < 8; k++) {
                float ee = __expf(p[k]) * w[k];
                denom += ee;
                accx = fmaf(ee, c[k].x, accx);
                accy = fmaf(ee, c[k].y, accy);
            }
        }
    }

    float inv = (end > start) ? 1.f / denom : 0.f;

    float2 xres = *reinterpret_cast<const float2*>(x + i0);
    float2 b2   = *reinterpret_cast<const float2*>(bias + 2 * lane);
    float v0 = fmaf(accx, inv, b2.x + xres.x);
    float v1 = fmaf(accy, inv, b2.y + xres.y);

    float sum = v0 + v1;
    float ssq = v0 * v0 + v1 * v1;
#pragma unroll
    for (int o = 16; o; o >>= 1) {
        sum += __shfl_xor_sync(0xFFFFFFFFu, sum, o);
        ssq += __shfl_xor_sync(0xFFFFFFFFu, ssq, o);
    }
    float mean = sum * (1.f / 64.f);
    float var  = ssq * (1.f / 64.f) - mean * mean;
    float rstd = rsqrtf(var + LN_EPS);

    float2 g2  = *reinterpret_cast<const float2*>(gamma + 2 * lane);
    float2 be2 = *reinterpret_cast<const float2*>(beta + 2 * lane);
    float o0 = fmaf((v0 - mean) * rstd, g2.x, be2.x);
    float o1 = fmaf((v1 - mean) * rstd, g2.y, be2.y);
    float2 r;
    r.x = o0 > 0.f ? o0 : expm1f(o0);
    r.y = o1 > 0.f ? o1 : expm1f(o1);
    *reinterpret_cast<float2*>(out + i0) = r;
}

extern "C" void kernel_launch(void* const* d_in, const int* in_sizes, int n_in,
                              void* d_out, int out_size) {
    const float* x     = (const float*)d_in[0];
    const int*   ei    = (const int*)  d_in[1];
    const float* Wl    = (const float*)d_in[2];
    const float* bl    = (const float*)d_in[3];
    const float* Wr    = (const float*)d_in[4];
    const float* br    = (const float*)d_in[5];
    const float* att   = (const float*)d_in[6];
    const float* bias  = (const float*)d_in[7];
    const float* gamma = (const float*)d_in[8];
    const float* beta  = (const float*)d_in[9];
    float* out = (float*)d_out;

    int n = in_sizes[0] / 64;
    int E = in_sizes[1] / 2;
    const int* src = ei;
    const int* dst = ei + E;
    int ntiles = (n + 1023) / 1024;   // 49 for n=50000 (<=148: grid barrier safe)

    linear_hist_kernel<<<(n + 63) / 64, 256>>>(x, Wl, bl, Wr, br, dst, n, E);
    scan1_kernel<<<ntiles, 1024>>>(n);
    scan3_scatter_kernel<<<ntiles, 1024>>>(src, dst, n, E);
    gat_node_kernel<<<((long long)n * 32 + 255) / 256, 256>>>(x, att, bias, gamma, beta, out, n);
}

// round 6
// speedup vs baseline: 1.2008x; 1.2008x over previous
#include <cuda_runtime.h>

#define NEG_SLOPE 0.2f
#define LN_EPS 1e-5f

static const int MAXN = 50000;
static const int MAXE = 800000;

// Scratch (allocation-free: __device__ globals; BSS zero-init at load)
__device__ float g_xl[MAXN * 64];
__device__ float g_xr[MAXN * 64];
__device__ int   g_deg[MAXN];      // invariant: zero at kernel_launch entry
__device__ int   g_scan[MAXN];
__device__ int   g_ptr[MAXN + 1];
__device__ int   g_fill[MAXN];
__device__ int   g_csrc[MAXE];
__device__ int   g_tilesum[128];

// ---------------------------------------------------------------------------
// K1: xl = x@Wl + bl, xr = x@Wr + br.  8 nodes per warp (weights amortized in
// registers, fma.rn.f32x2 packed), 64 nodes per 256-thread block.
// Tail: fused in-degree histogram (g_deg zero at entry; K3 restores).
// ---------------------------------------------------------------------------
__global__ void linear_hist_kernel(const float* __restrict__ x,
                                   const float* __restrict__ Wl, const float* __restrict__ bl,
                                   const float* __restrict__ Wr, const float* __restrict__ br,
                                   const int* __restrict__ dst,
                                   int n, int E) {
    __shared__ __align__(16) float sWl[64 * 64];
    __shared__ __align__(16) float sWr[64 * 64];
    __shared__ __align__(16) float sx[64 * 64];
    int tid = threadIdx.x;
    for (int i = tid; i < 4096; i += 256) { sWl[i] = Wl[i]; sWr[i] = Wr[i]; }

    int base = blockIdx.x * 64;
    for (int i = tid; i < 4096; i += 256) {
        int nn = base + (i >> 6);
        sx[i] = (nn < n) ? x[nn * 64 + (i & 63)] : 0.f;
    }
    __syncthreads();

    int w = tid >> 5;
    int j = tid & 31;
    {
        unsigned long long accl[8], accr[8];
#pragma unroll
        for (int k = 0; k < 8; k++) { accl[k] = 0ull; accr[k] = 0ull; }

        const unsigned long long* wl2 = reinterpret_cast<const unsigned long long*>(sWl + 2 * j);
        const unsigned long long* wr2 = reinterpret_cast<const unsigned long long*>(sWr + 2 * j);
        const float* xv = sx + (w * 8) * 64;

#pragma unroll 8
        for (int c = 0; c < 64; c++) {
            unsigned long long wl = wl2[c * 32];
            unsigned long long wr = wr2[c * 32];
#pragma unroll
            for (int k = 0; k < 8; k++) {
                float xc = xv[k * 64 + c];
                unsigned long long x2;
                asm("mov.b64 %0, {%1, %1};" : "=l"(x2) : "f"(xc));
                asm("fma.rn.f32x2 %0, %1, %2, %0;" : "+l"(accl[k]) : "l"(x2), "l"(wl));
                asm("fma.rn.f32x2 %0, %1, %2, %0;" : "+l"(accr[k]) : "l"(x2), "l"(wr));
            }
        }

        float2 bl2 = *reinterpret_cast<const float2*>(bl + 2 * j);
        float2 br2 = *reinterpret_cast<const float2*>(br + 2 * j);
#pragma unroll
        for (int k = 0; k < 8; k++) {
            int nn = base + w * 8 + k;
            if (nn < n) {
                float l0, l1, r0, r1;
                asm("mov.b64 {%0, %1}, %2;" : "=f"(l0), "=f"(l1) : "l"(accl[k]));
                asm("mov.b64 {%0, %1}, %2;" : "=f"(r0), "=f"(r1) : "l"(accr[k]));
                *reinterpret_cast<float2*>(g_xl + nn * 64 + 2 * j) =
                    make_float2(l0 + bl2.x, l1 + bl2.y);
                *reinterpret_cast<float2*>(g_xr + nn * 64 + 2 * j) =
                    make_float2(r0 + br2.x, r1 + br2.y);
            }
        }
    }

    // fused in-degree histogram (grid-stride over edges)
    int stride = gridDim.x * 256;
    for (int e = blockIdx.x * 256 + tid; e < E; e += stride)
        atomicAdd(&g_deg[dst[e]], 1);
}

// ---------------------------------------------------------------------------
// K2: per-tile (1024) inclusive scan of g_deg -> g_scan; tile totals.
// ---------------------------------------------------------------------------
__global__ void scan1_kernel(int n) {
    __shared__ int wsum[32];
    int gid = blockIdx.x * 1024 + threadIdx.x;
    int lane = threadIdx.x & 31, wid = threadIdx.x >> 5;
    int v = (gid < n) ? g_deg[gid] : 0;
    int s = v;
#pragma unroll
    for (int o = 1; o < 32; o <<= 1) {
        int t = __shfl_up_sync(0xFFFFFFFFu, s, o);
        if (lane >= o) s += t;
    }
    if (lane == 31) wsum[wid] = s;
    __syncthreads();
    if (wid == 0) {
        int wv = wsum[lane];
#pragma unroll
        for (int o = 1; o < 32; o <<= 1) {
            int t = __shfl_up_sync(0xFFFFFFFFu, wv, o);
            if (lane >= o) wv += t;
        }
        wsum[lane] = wv;
    }
    __syncthreads();
    int incl = s + (wid ? wsum[wid - 1] : 0);
    if (gid < n) g_scan[gid] = incl;
    if (threadIdx.x == 1023) g_tilesum[blockIdx.x] = incl;
}

// ---------------------------------------------------------------------------
// K3: per-block tile-offset, apply -> g_ptr (exclusive), g_fill; re-zero g_deg.
// ---------------------------------------------------------------------------
__global__ void scan3_kernel(int n) {
    __shared__ int s_off;
    int t = threadIdx.x;
    if (t < 32) {
        int acc = 0;
        for (int i = t; i < blockIdx.x; i += 32) acc += g_tilesum[i];
#pragma unroll
        for (int o = 16; o; o >>= 1) acc += __shfl_xor_sync(0xFFFFFFFFu, acc, o);
        if (t == 0) s_off = acc;
    }
    __syncthreads();
    int gid = blockIdx.x * 1024 + t;
    if (gid < n) {
        int incl = g_scan[gid] + s_off;
        int excl = incl - g_deg[gid];
        g_ptr[gid]  = excl;
        g_fill[gid] = excl;
        g_deg[gid]  = 0;            // restore invariant for next launch
        if (gid == n - 1) g_ptr[n] = incl;
    }
}

// ---------------------------------------------------------------------------
// K4: scatter edge sources into CSR order by dst (8 edges in flight/thread).
// ---------------------------------------------------------------------------
__global__ void scatter_kernel(const int* __restrict__ src, const int* __restrict__ dst, int E) {
    long long i = (long long)(blockIdx.x * blockDim.x + threadIdx.x) * 8;
    if (i + 7 < E) {
        int4 d4a = *reinterpret_cast<const int4*>(dst + i);
        int4 d4b = *reinterpret_cast<const int4*>(dst + i + 4);
        int4 s4a = *reinterpret_cast<const int4*>(src + i);
        int4 s4b = *reinterpret_cast<const int4*>(src + i + 4);
        int p0 = atomicAdd(&g_fill[d4a.x], 1);
        int p1 = atomicAdd(&g_fill[d4a.y], 1);
        int p2 = atomicAdd(&g_fill[d4a.z], 1);
        int p3 = atomicAdd(&g_fill[d4a.w], 1);
        int p4 = atomicAdd(&g_fill[d4b.x], 1);
        int p5 = atomicAdd(&g_fill[d4b.y], 1);
        int p6 = atomicAdd(&g_fill[d4b.z], 1);
        int p7 = atomicAdd(&g_fill[d4b.w], 1);
        g_csrc[p0] = s4a.x;
        g_csrc[p1] = s4a.y;
        g_csrc[p2] = s4a.z;
        g_csrc[p3] = s4a.w;
        g_csrc[p4] = s4b.x;
        g_csrc[p5] = s4b.y;
        g_csrc[p6] = s4b.z;
        g_csrc[p7] = s4b.w;
    } else {
        for (long long e = i; e < E; e++) {
            int p = atomicAdd(&g_fill[dst[e]], 1);
            g_csrc[p] = src[e];
        }
    }
}

// ---------------------------------------------------------------------------
// K5: fused GAT aggregation + bias + residual + LayerNorm + ELU.
// TWO nodes per warp (one per half-warp), 4 channels/lane (float4).
// Head = 4 lanes -> 2-stage shuffle reduce. leaky(z) = 0.6z + 0.4|z| folded
// into the attention dot product.
// ---------------------------------------------------------------------------
__global__ void gat_node_kernel(const float* __restrict__ x, const float* __restrict__ att,
                                const float* __restrict__ bias, const float* __restrict__ gamma,
                                const float* __restrict__ beta, float* __restrict__ out, int n) {
    int warp = (blockIdx.x * blockDim.x + threadIdx.x) >> 5;
    int lane = threadIdx.x & 31;
    if (warp * 2 >= n) return;              // whole warp out of range
    int hl   = lane & 15;                   // lane within node
    int half = lane >> 4;                   // 0/1 -> which node
    int d = warp * 2 + half;
    bool active = d < n;
    int dd = active ? d : (n - 1);

    const float4* xl4 = reinterpret_cast<const float4*>(g_xl);
    float4 xr4  = __ldg(reinterpret_cast<const float4*>(g_xr) + dd * 16 + hl);
    float4 att4 = *(reinterpret_cast<const float4*>(att) + hl);
    float4 a06 = make_float4(att4.x * 0.6f, att4.y * 0.6f, att4.z * 0.6f, att4.w * 0.6f);
    float4 a04 = make_float4(att4.x * 0.4f, att4.y * 0.4f, att4.z * 0.4f, att4.w * 0.4f);

    int start = __ldg(&g_ptr[dd]);
    int end   = active ? __ldg(&g_ptr[dd + 1]) : start;
    int deg   = end - start;
    int tiles = (deg + 15) >> 4;
    int maxt  = max(tiles, __shfl_xor_sync(0xFFFFFFFFu, tiles, 16));

    float ax = 0.f, ay = 0.f, az = 0.f, aw = 0.f, denom = 0.f;

    for (int t = 0; t < maxt; t++) {
        int tb  = start + t * 16;
        int cnt = end - tb;
        cnt = cnt < 0 ? 0 : (cnt > 16 ? 16 : cnt);
        int sv = (hl < cnt) ? __ldg(&g_csrc[tb + hl]) : 0;
        int mc = max(cnt, __shfl_xor_sync(0xFFFFFFFFu, cnt, 16));

        for (int j = 0; j < mc; j += 4) {
            float4 c[4];
            float  p[4], wv[4];
#pragma unroll
            for (int k = 0; k < 4; k++) {
                int s = __shfl_sync(0xFFFFFFFFu, sv, (lane & 16) + j + k);
                c[k] = __ldg(xl4 + s * 16 + hl);
                wv[k] = (j + k < cnt) ? 1.f : 0.f;
            }
#pragma unroll
            for (int k = 0; k < 4; k++) {
                float zx = c[k].x + xr4.x;
                float zy = c[k].y + xr4.y;
                float zz = c[k].z + xr4.z;
                float zw = c[k].w + xr4.w;
                float pv;
                pv = fmaf(a04.x, fabsf(zx), a06.x * zx);
                pv = fmaf(a06.y, zy, pv); pv = fmaf(a04.y, fabsf(zy), pv);
                pv = fmaf(a06.z, zz, pv); pv = fmaf(a04.z, fabsf(zz), pv);
                pv = fmaf(a06.w, zw, pv); pv = fmaf(a04.w, fabsf(zw), pv);
                p[k] = pv;
            }
#pragma unroll
            for (int k = 0; k < 4; k++) p[k] += __shfl_xor_sync(0xFFFFFFFFu, p[k], 1);
#pragma unroll
            for (int k = 0; k < 4; k++) p[k] += __shfl_xor_sync(0xFFFFFFFFu, p[k], 2);
#pragma unroll
            for (int k = 0; k < 4; k++) {
                float ee = __expf(p[k]) * wv[k];
                denom += ee;
                ax = fmaf(ee, c[k].x, ax);
                ay = fmaf(ee, c[k].y, ay);
                az = fmaf(ee, c[k].z, az);
                aw = fmaf(ee, c[k].w, aw);
            }
        }
    }

    float inv = (deg > 0) ? 1.f / denom : 0.f;

    float4 xres = __ldg(reinterpret_cast<const float4*>(x) + dd * 16 + hl);
    float4 b4   = *(reinterpret_cast<const float4*>(bias) + hl);
    float v0 = fmaf(ax, inv, b4.x + xres.x);
    float v1 = fmaf(ay, inv, b4.y + xres.y);
    float v2 = fmaf(az, inv, b4.z + xres.z);
    float v3 = fmaf(aw, inv, b4.w + xres.w);

    float sum = (v0 + v1) + (v2 + v3);
    float ssq = fmaf(v0, v0, v1 * v1) + fmaf(v2, v2, v3 * v3);
#pragma unroll
    for (int o = 1; o < 16; o <<= 1) {
        sum += __shfl_xor_sync(0xFFFFFFFFu, sum, o);
        ssq += __shfl_xor_sync(0xFFFFFFFFu, ssq, o);
    }
    float mean = sum * (1.f / 64.f);
    float var  = ssq * (1.f / 64.f) - mean * mean;
    float rstd = rsqrtf(var + LN_EPS);

    float4 g4  = *(reinterpret_cast<const float4*>(gamma) + hl);
    float4 be4 = *(reinterpret_cast<const float4*>(beta) + hl);
    float o0 = fmaf((v0 - mean) * rstd, g4.x, be4.x);
    float o1 = fmaf((v1 - mean) * rstd, g4.y, be4.y);
    float o2 = fmaf((v2 - mean) * rstd, g4.z, be4.z);
    float o3 = fmaf((v3 - mean) * rstd, g4.w, be4.w);
    float4 r;
    r.x = o0 > 0.f ? o0 : expm1f(o0);
    r.y = o1 > 0.f ? o1 : expm1f(o1);
    r.z = o2 > 0.f ? o2 : expm1f(o2);
    r.w = o3 > 0.f ? o3 : expm1f(o3);
    if (active) *(reinterpret_cast<float4*>(out) + d * 16 + hl) = r;
}

extern "C" void kernel_launch(void* const* d_in, const int* in_sizes, int n_in,
                              void* d_out, int out_size) {
    const float* x     = (const float*)d_in[0];
    const int*   ei    = (const int*)  d_in[1];
    const float* Wl    = (const float*)d_in[2];
    const float* bl    = (const float*)d_in[3];
    const float* Wr    = (const float*)d_in[4];
    const float* br    = (const float*)d_in[5];
    const float* att   = (const float*)d_in[6];
    const float* bias  = (const float*)d_in[7];
    const float* gamma = (const float*)d_in[8];
    const float* beta  = (const float*)d_in[9];
    float* out = (float*)d_out;

    int n = in_sizes[0] / 64;
    int E = in_sizes[1] / 2;
    const int* src = ei;
    const int* dst = ei + E;
    int ntiles = (n + 1023) / 1024;

    linear_hist_kernel<<<(n + 63) / 64, 256>>>(x, Wl, bl, Wr, br, dst, n, E);
    scan1_kernel<<<ntiles, 1024>>>(n);
    scan3_kernel<<<ntiles, 1024>>>(n);
    scatter_kernel<<<(E / 8 + 255) / 256 + 1, 256>>>(src, dst, E);
    int warps = (n + 1) / 2;
    gat_node_kernel<<<(warps * 32 + 255) / 256, 256>>>(x, att, bias, gamma, beta, out, n);
}

// round 7
// speedup vs baseline: 1.2579x; 1.0476x over previous
#include <cuda_runtime.h>

#define NEG_SLOPE 0.2f
#define LN_EPS 1e-5f

static const int MAXN = 50000;
static const int MAXE = 800000;

// Scratch (allocation-free: __device__ globals; BSS zero-init at load)
__device__ float g_xl[MAXN * 64];
__device__ float g_xr[MAXN * 64];
__device__ int   g_deg[MAXN];      // invariant: zero at kernel_launch entry
__device__ int   g_rank[MAXE];     // per-edge rank within its dst segment
__device__ int   g_scan[MAXN];
__device__ int   g_ptr[MAXN + 1];
__device__ int   g_csrc[MAXE];
__device__ int   g_tilesum[256];

// ---------------------------------------------------------------------------
// K1: xl = x@Wl + bl, xr = x@Wr + br.  8 nodes per warp (weights amortized in
// registers, fma.rn.f32x2 packed), 64 nodes per 256-thread block.
// Tail: fused in-degree histogram; atomicAdd return value = edge rank
// (g_deg zero at entry; scan3 restores).
// ---------------------------------------------------------------------------
__global__ void linear_hist_kernel(const float* __restrict__ x,
                                   const float* __restrict__ Wl, const float* __restrict__ bl,
                                   const float* __restrict__ Wr, const float* __restrict__ br,
                                   const int* __restrict__ dst,
                                   int n, int E) {
    __shared__ __align__(16) float sWl[64 * 64];
    __shared__ __align__(16) float sWr[64 * 64];
    __shared__ __align__(16) float sx[64 * 64];
    int tid = threadIdx.x;
    for (int i = tid; i < 4096; i += 256) { sWl[i] = Wl[i]; sWr[i] = Wr[i]; }

    int base = blockIdx.x * 64;
    for (int i = tid; i < 4096; i += 256) {
        int nn = base + (i >> 6);
        sx[i] = (nn < n) ? x[nn * 64 + (i & 63)] : 0.f;
    }
    __syncthreads();

    int w = tid >> 5;
    int j = tid & 31;
    {
        unsigned long long accl[8], accr[8];
#pragma unroll
        for (int k = 0; k < 8; k++) { accl[k] = 0ull; accr[k] = 0ull; }

        const unsigned long long* wl2 = reinterpret_cast<const unsigned long long*>(sWl + 2 * j);
        const unsigned long long* wr2 = reinterpret_cast<const unsigned long long*>(sWr + 2 * j);
        const float* xv = sx + (w * 8) * 64;

#pragma unroll 8
        for (int c = 0; c < 64; c++) {
            unsigned long long wl = wl2[c * 32];
            unsigned long long wr = wr2[c * 32];
#pragma unroll
            for (int k = 0; k < 8; k++) {
                float xc = xv[k * 64 + c];
                unsigned long long x2;
                asm("mov.b64 %0, {%1, %1};" : "=l"(x2) : "f"(xc));
                asm("fma.rn.f32x2 %0, %1, %2, %0;" : "+l"(accl[k]) : "l"(x2), "l"(wl));
                asm("fma.rn.f32x2 %0, %1, %2, %0;" : "+l"(accr[k]) : "l"(x2), "l"(wr));
            }
        }

        float2 bl2 = *reinterpret_cast<const float2*>(bl + 2 * j);
        float2 br2 = *reinterpret_cast<const float2*>(br + 2 * j);
#pragma unroll
        for (int k = 0; k < 8; k++) {
            int nn = base + w * 8 + k;
            if (nn < n) {
                float l0, l1, r0, r1;
                asm("mov.b64 {%0, %1}, %2;" : "=f"(l0), "=f"(l1) : "l"(accl[k]));
                asm("mov.b64 {%0, %1}, %2;" : "=f"(r0), "=f"(r1) : "l"(accr[k]));
                *reinterpret_cast<float2*>(g_xl + nn * 64 + 2 * j) =
                    make_float2(l0 + bl2.x, l1 + bl2.y);
                *reinterpret_cast<float2*>(g_xr + nn * 64 + 2 * j) =
                    make_float2(r0 + br2.x, r1 + br2.y);
            }
        }
    }

    // fused in-degree histogram; record per-edge rank (atomic return value).
    // Thread t handles edges [4t, 4t+4): 4 independent atomics in flight.
    long long i = (long long)(blockIdx.x * 256 + tid) * 4;
    if (i + 3 < E) {
        int4 d4 = *reinterpret_cast<const int4*>(dst + i);
        int r0 = atomicAdd(&g_deg[d4.x], 1);
        int r1 = atomicAdd(&g_deg[d4.y], 1);
        int r2 = atomicAdd(&g_deg[d4.z], 1);
        int r3 = atomicAdd(&g_deg[d4.w], 1);
        *reinterpret_cast<int4*>(g_rank + i) = make_int4(r0, r1, r2, r3);
    } else {
        for (long long e = i; e < E; e++)
            g_rank[e] = atomicAdd(&g_deg[dst[e]], 1);
    }
}

// ---------------------------------------------------------------------------
// K2: per-tile (256) inclusive scan of g_deg -> g_scan; tile totals.
// ---------------------------------------------------------------------------
__global__ void scan1_kernel(int n) {
    __shared__ int wsum[8];
    int gid = blockIdx.x * 256 + threadIdx.x;
    int lane = threadIdx.x & 31, wid = threadIdx.x >> 5;
    int v = (gid < n) ? g_deg[gid] : 0;
    int s = v;
#pragma unroll
    for (int o = 1; o < 32; o <<= 1) {
        int t = __shfl_up_sync(0xFFFFFFFFu, s, o);
        if (lane >= o) s += t;
    }
    if (lane == 31) wsum[wid] = s;
    __syncthreads();
    if (threadIdx.x < 32) {
        int wv = (lane < 8) ? wsum[lane] : 0;
#pragma unroll
        for (int o = 1; o < 8; o <<= 1) {
            int t = __shfl_up_sync(0xFFFFFFFFu, wv, o);
            if (lane >= o) wv += t;
        }
        if (lane < 8) wsum[lane] = wv;
    }
    __syncthreads();
    int incl = s + (wid ? wsum[wid - 1] : 0);
    if (gid < n) g_scan[gid] = incl;
    if (threadIdx.x == 255) g_tilesum[blockIdx.x] = incl;
}

// ---------------------------------------------------------------------------
// K3: per-block tile-offset, apply -> g_ptr (exclusive); re-zero g_deg.
// ---------------------------------------------------------------------------
__global__ void scan3_kernel(int n) {
    __shared__ int s_off;
    int t = threadIdx.x;
    if (t < 32) {
        int acc = 0;
        for (int i = t; i < blockIdx.x; i += 32) acc += g_tilesum[i];
#pragma unroll
        for (int o = 16; o; o >>= 1) acc += __shfl_xor_sync(0xFFFFFFFFu, acc, o);
        if (t == 0) s_off = acc;
    }
    __syncthreads();
    int gid = blockIdx.x * 256 + t;
    if (gid < n) {
        int incl = g_scan[gid] + s_off;
        g_ptr[gid] = incl - g_deg[gid];
        g_deg[gid] = 0;             // restore invariant for next launch
        if (gid == n - 1) g_ptr[n] = incl;
    }
}

// ---------------------------------------------------------------------------
// K4: atomic-free CSR scatter: csrc[ptr[dst] + rank] = src. 4 edges/thread.
// ---------------------------------------------------------------------------
__global__ void scatter_kernel(const int* __restrict__ src, const int* __restrict__ dst, int E) {
    long long i = (long long)(blockIdx.x * blockDim.x + threadIdx.x) * 4;
    if (i + 3 < E) {
        int4 d4 = *reinterpret_cast<const int4*>(dst + i);
        int4 r4 = *reinterpret_cast<const int4*>(g_rank + i);
        int4 s4 = *reinterpret_cast<const int4*>(src + i);
        int p0 = __ldg(&g_ptr[d4.x]) + r4.x;
        int p1 = __ldg(&g_ptr[d4.y]) + r4.y;
        int p2 = __ldg(&g_ptr[d4.z]) + r4.z;
        int p3 = __ldg(&g_ptr[d4.w]) + r4.w;
        g_csrc[p0] = s4.x;
        g_csrc[p1] = s4.y;
        g_csrc[p2] = s4.z;
        g_csrc[p3] = s4.w;
    } else {
        for (long long e = i; e < E; e++)
            g_csrc[__ldg(&g_ptr[dst[e]]) + g_rank[e]] = src[e];
    }
}

// ---------------------------------------------------------------------------
// K5: fused GAT aggregation + bias + residual + LayerNorm + ELU.
// TWO nodes per warp (one per half-warp), 4 channels/lane (float4).
// Head = 4 lanes -> 2-stage shuffle reduce. leaky(z) = 0.6z + 0.4|z| folded
// into the attention dot product.
// ---------------------------------------------------------------------------
__global__ void gat_node_kernel(const float* __restrict__ x, const float* __restrict__ att,
                                const float* __restrict__ bias, const float* __restrict__ gamma,
                                const float* __restrict__ beta, float* __restrict__ out, int n) {
    int warp = (blockIdx.x * blockDim.x + threadIdx.x) >> 5;
    int lane = threadIdx.x & 31;
    if (warp * 2 >= n) return;
    int hl   = lane & 15;
    int half = lane >> 4;
    int d = warp * 2 + half;
    bool active = d < n;
    int dd = active ? d : (n - 1);

    const float4* xl4 = reinterpret_cast<const float4*>(g_xl);
    float4 xr4  = __ldg(reinterpret_cast<const float4*>(g_xr) + dd * 16 + hl);
    float4 att4 = *(reinterpret_cast<const float4*>(att) + hl);
    float4 a06 = make_float4(att4.x * 0.6f, att4.y * 0.6f, att4.z * 0.6f, att4.w * 0.6f);
    float4 a04 = make_float4(att4.x * 0.4f, att4.y * 0.4f, att4.z * 0.4f, att4.w * 0.4f);

    int start = __ldg(&g_ptr[dd]);
    int end   = active ? __ldg(&g_ptr[dd + 1]) : start;
    int deg   = end - start;
    int tiles = (deg + 15) >> 4;
    int maxt  = max(tiles, __shfl_xor_sync(0xFFFFFFFFu, tiles, 16));

    float ax = 0.f, ay = 0.f, az = 0.f, aw = 0.f, denom = 0.f;

    for (int t = 0; t < maxt; t++) {
        int tb  = start + t * 16;
        int cnt = end - tb;
        cnt = cnt < 0 ? 0 : (cnt > 16 ? 16 : cnt);
        int sv = (hl < cnt) ? __ldg(&g_csrc[tb + hl]) : 0;
        int mc = max(cnt, __shfl_xor_sync(0xFFFFFFFFu, cnt, 16));

        for (int j = 0; j < mc; j += 4) {
            float4 c[4];
            float  p[4], wv[4];
#pragma unroll
            for (int k = 0; k < 4; k++) {
                int s = __shfl_sync(0xFFFFFFFFu, sv, (lane & 16) + j + k);
                c[k] = __ldg(xl4 + s * 16 + hl);
                wv[k] = (j + k < cnt) ? 1.f : 0.f;
            }
#pragma unroll
            for (int k = 0; k < 4; k++) {
                float zx = c[k].x + xr4.x;
                float zy = c[k].y + xr4.y;
                float zz = c[k].z + xr4.z;
                float zw = c[k].w + xr4.w;
                float pv;
                pv = fmaf(a04.x, fabsf(zx), a06.x * zx);
                pv = fmaf(a06.y, zy, pv); pv = fmaf(a04.y, fabsf(zy), pv);
                pv = fmaf(a06.z, zz, pv); pv = fmaf(a04.z, fabsf(zz), pv);
                pv = fmaf(a06.w, zw, pv); pv = fmaf(a04.w, fabsf(zw), pv);
                p[k] = pv;
            }
#pragma unroll
            for (int k = 0; k < 4; k++) p[k] += __shfl_xor_sync(0xFFFFFFFFu, p[k], 1);
#pragma unroll
            for (int k = 0; k < 4; k++) p[k] += __shfl_xor_sync(0xFFFFFFFFu, p[k], 2);
#pragma unroll
            for (int k = 0; k < 4; k++) {
                float ee = __expf(p[k]) * wv[k];
                denom += ee;
                ax = fmaf(ee, c[k].x, ax);
                ay = fmaf(ee, c[k].y, ay);
                az = fmaf(ee, c[k].z, az);
                aw = fmaf(ee, c[k].w, aw);
            }
        }
    }

    float inv = (deg > 0) ? 1.f / denom : 0.f;

    float4 xres = __ldg(reinterpret_cast<const float4*>(x) + dd * 16 + hl);
    float4 b4   = *(reinterpret_cast<const float4*>(bias) + hl);
    float v0 = fmaf(ax, inv, b4.x + xres.x);
    float v1 = fmaf(ay, inv, b4.y + xres.y);
    float v2 = fmaf(az, inv, b4.z + xres.z);
    float v3 = fmaf(aw, inv, b4.w + xres.w);

    float sum = (v0 + v1) + (v2 + v3);
    float ssq = fmaf(v0, v0, v1 * v1) + fmaf(v2, v2, v3 * v3);
#pragma unroll
    for (int o = 1; o < 16; o <<= 1) {
        sum += __shfl_xor_sync(0xFFFFFFFFu, sum, o);
        ssq += __shfl_xor_sync(0xFFFFFFFFu, ssq, o);
    }
    float mean = sum * (1.f / 64.f);
    float var  = ssq * (1.f / 64.f) - mean * mean;
    float rstd = rsqrtf(var + LN_EPS);

    float4 g4  = *(reinterpret_cast<const float4*>(gamma) + hl);
    float4 be4 = *(reinterpret_cast<const float4*>(beta) + hl);
    float o0 = fmaf((v0 - mean) * rstd, g4.x, be4.x);
    float o1 = fmaf((v1 - mean) * rstd, g4.y, be4.y);
    float o2 = fmaf((v2 - mean) * rstd, g4.z, be4.z);
    float o3 = fmaf((v3 - mean) * rstd, g4.w, be4.w);
    float4 r;
    r.x = o0 > 0.f ? o0 : expm1f(o0);
    r.y = o1 > 0.f ? o1 : expm1f(o1);
    r.z = o2 > 0.f ? o2 : expm1f(o2);
    r.w = o3 > 0.f ? o3 : expm1f(o3);
    if (active) *(reinterpret_cast<float4*>(out) + d * 16 + hl) = r;
}

extern "C" void kernel_launch(void* const* d_in, const int* in_sizes, int n_in,
                              void* d_out, int out_size) {
    const float* x     = (const float*)d_in[0];
    const int*   ei    = (const int*)  d_in[1];
    const float* Wl    = (const float*)d_in[2];
    const float* bl    = (const float*)d_in[3];
    const float* Wr    = (const float*)d_in[4];
    const float* br    = (const float*)d_in[5];
    const float* att   = (const float*)d_in[6];
    const float* bias  = (const float*)d_in[7];
    const float* gamma = (const float*)d_in[8];
    const float* beta  = (const float*)d_in[9];
    float* out = (float*)d_out;

    int n = in_sizes[0] / 64;
    int E = in_sizes[1] / 2;
    const int* src = ei;
    const int* dst = ei + E;
    int ntiles = (n + 255) / 256;

    int lin_blocks = (n + 63) / 64;
    int hist_blocks = (int)((E + 3LL) / 4 + 255) / 256;
    if (lin_blocks < hist_blocks) lin_blocks = hist_blocks;   // cover all edges

    linear_hist_kernel<<<lin_blocks, 256>>>(x, Wl, bl, Wr, br, dst, n, E);
    scan1_kernel<<<ntiles, 256>>>(n);
    scan3_kernel<<<ntiles, 256>>>(n);
    scatter_kernel<<<(int)((E + 3LL) / 4 + 255) / 256, 256>>>(src, dst, E);
    int warps = (n + 1) / 2;
    gat_node_kernel<<<(warps * 32 + 255) / 256, 256>>>(x, att, bias, gamma, beta, out, n);
}